// round 10
// baseline (speedup 1.0000x reference)
#include <cuda_runtime.h>

// RoIPooling2D (Caffe roi_pool, max) — single-kernel smem-window version.
// x [B=2,C=256,H=50,W=50] f32, rois [N,5], out [N,256,7,7] f32.
// Bounds replicate XLA:GPU arithmetic exactly (div.full.f32, proven Round 3).
//
// Block = (roi n, 64-channel quarter), 512 threads.
//  Phase 1: stream ROI window (<=18x18 px, 64 ch) from NCHW x into smem,
//           transposed to [px][c] with stride 65 (conflict-free STS/LDS).
//           All loads independent -> no L2 latency chains.
//  Phase 2: thread = (c,bin) outputs from smem (LDS ~29cyc), contiguous STG.

#define POOL_H 7
#define POOL_W 7
#define NBINS  (POOL_H * POOL_W)       // 49
#define SPATIAL_SCALE 0.0625f
#define C_TOT  256
#define HDIM   50
#define WDIM   50
#define HW     (HDIM * WDIM)
#define CQ     64                      // channels per block (quarter)
#define WIN    20                      // max window rows/cols (proven <=18)
#define SSTRIDE 65                     // smem floats per px (64 + 1 pad)
#define GTHREADS 512
#define NWARPS (GTHREADS / 32)
#define SMEM_BYTES (WIN * WIN * SSTRIDE * 4)   // 104,000 B
#define NEG_FLT_MAX (-3.402823466e38f)

__device__ __forceinline__ float div_full(float a, float b) {
    float r;
    asm("div.full.f32 %0, %1, %2;" : "=f"(r) : "f"(a), "f"(b));
    return r;
}

__global__ void __launch_bounds__(GTHREADS)
roi_pool_kernel(const float* __restrict__ x, const float* __restrict__ rois,
                float* __restrict__ out, int N) {
    extern __shared__ float s_win[];               // [WIN*WIN][SSTRIDE]
    __shared__ int s_hs[POOL_H], s_he[POOL_H], s_ws[POOL_W], s_we[POOL_W];
    __shared__ int s_b;

    int n   = blockIdx.x;
    int q   = blockIdx.y;                          // channel quarter
    int c0  = q * CQ;
    int tid = threadIdx.x;
    int warp = tid >> 5;
    int lane = tid & 31;

    // --- bounds (exact replica of reference arithmetic, incl. div.full) ---
    if (tid < POOL_H + POOL_W + 1) {
        const float* r = rois + n * 5;
        if (tid == POOL_H + POOL_W) {
            s_b = (int)r[0];
        } else {
            bool is_h = (tid < POOL_H);
            int  i    = is_h ? tid : tid - POOL_H;
            float s1  = rintf(__fmul_rn(r[is_h ? 2 : 1], SPATIAL_SCALE));
            float e1  = rintf(__fmul_rn(r[is_h ? 4 : 3], SPATIAL_SCALE));
            float sz  = fmaxf(__fadd_rn(__fsub_rn(e1, s1), 1.0f), 1.0f);
            float bs  = div_full(sz, is_h ? (float)POOL_H : (float)POOL_W);
            float npx = is_h ? (float)HDIM : (float)WDIM;
            float lo = __fadd_rn(floorf(__fmul_rn((float)i, bs)), s1);
            float hi = __fadd_rn(ceilf(__fmul_rn((float)(i + 1), bs)), s1);
            lo = fminf(fmaxf(lo, 0.0f), npx);
            hi = fminf(fmaxf(hi, 0.0f), npx);
            if (is_h) { s_hs[i] = (int)lo; s_he[i] = (int)hi; }
            else      { s_ws[i] = (int)lo; s_we[i] = (int)hi; }
        }
    }
    __syncthreads();

    int h0 = s_hs[0], h1 = s_he[POOL_H - 1];
    int w0 = s_ws[0], w1 = s_we[POOL_W - 1];
    int span_h = min(max(h1 - h0, 0), WIN);
    int span_w = min(max(w1 - w0, 0), WIN);
    int b = s_b;

    // --- Phase 1: stream window into smem, transposed. task t = lh*64 + c ---
    {
        const float* xq = x + ((size_t)b * C_TOT + c0) * HW;
        int tasks = span_h * CQ;
        for (int t = warp; t < tasks; t += NWARPS) {
            int lh = t >> 6;            // window row
            int c  = t & 63;            // local channel
            if (lane < span_w) {
                float v = __ldg(xq + (size_t)c * HW + (h0 + lh) * WDIM + w0 + lane);
                s_win[((lh * WIN) + lane) * SSTRIDE + c] = v;
            }
        }
    }
    __syncthreads();

    // --- Phase 2: thread = (c, bin); gather from smem; contiguous STG ---
    float* obase = out + (size_t)n * (C_TOT * NBINS) + (size_t)c0 * NBINS;
    const int total = CQ * NBINS;                  // 3136
    for (int i = tid; i < total; i += GTHREADS) {
        int c   = i / NBINS;                       // const divisor
        int bin = i - c * NBINS;
        int ph  = bin / POOL_W;                    // const divisor
        int pw  = bin - ph * POOL_W;

        int hs = s_hs[ph], he = min(s_he[ph], h0 + WIN);
        int ws = s_ws[pw], we = min(s_we[pw], w0 + WIN);

        float m = NEG_FLT_MAX;
        bool empty = (he <= hs) || (we <= ws);
        if (!empty) {
            const float* rowp = s_win
                + ((size_t)(hs - h0) * WIN + (ws - w0)) * SSTRIDE + c;
            int ww = we - ws;
            for (int h = hs; h < he; ++h) {
                const float* p = rowp;
                for (int w = 0; w < ww; ++w) {
                    m = fmaxf(m, *p);
                    p += SSTRIDE;
                }
                rowp += WIN * SSTRIDE;
            }
        } else {
            m = 0.0f;
        }
        obase[i] = m;
    }
}

extern "C" void kernel_launch(void* const* d_in, const int* in_sizes, int n_in,
                              void* d_out, int out_size) {
    const float* x    = (const float*)d_in[0];   // [B,256,50,50]
    const float* rois = (const float*)d_in[1];   // [N,5]
    float* out = (float*)d_out;                  // [N,256,7,7]

    const int N = in_sizes[1] / 5;

    static int configured = 0;                   // idempotent attribute set
    if (!configured) {
        cudaFuncSetAttribute(roi_pool_kernel,
                             cudaFuncAttributeMaxDynamicSharedMemorySize,
                             SMEM_BYTES);
        configured = 1;
    }

    dim3 grid(N, C_TOT / CQ);                    // (128, 4) = 512 blocks
    roi_pool_kernel<<<grid, GTHREADS, SMEM_BYTES>>>(x, rois, out, N);
}

// round 11
// speedup vs baseline: 1.9611x; 1.9611x over previous
#include <cuda_runtime.h>

// RoIPooling2D (Caffe roi_pool, max) — NHWC gather, single-exposure bins.
// x [B=2,C=256,H=50,W=50] f32, rois [N,5], out [N,256,7,7] f32.
// Bounds replicate XLA:GPU arithmetic exactly (div.full.f32, proven Round 3).
//
// Key idea: bin windows are provably <=4x4 here, so each (bin, 64ch) warp-unit
// issues a FULL 4x4 grid of unconditional float2 loads with clamped indices
// (min(d, extent-1)); duplicates are no-ops under max. 16 independent loads
// -> ONE L2 latency exposure per unit (vs ~5 serialized in R4/R7/R9).

#define POOL_H 7
#define POOL_W 7
#define NBINS  (POOL_H * POOL_W)       // 49
#define SPATIAL_SCALE 0.0625f
#define C_TOT  256
#define HDIM   50
#define WDIM   50
#define HW     (HDIM * WDIM)
#define CH     128                     // channels per gather block (half)
#define NUNITS (NBINS * 2)             // 98: (bin, 64-ch sub-half)
#define GTHREADS 512
#define NWARPS (GTHREADS / 32)
#define NEG_FLT_MAX (-3.402823466e38f)

__device__ float g_xt[2 * HW * C_TOT];  // NHWC scratch, 5.12 MB

__device__ __forceinline__ float div_full(float a, float b) {
    float r;
    asm("div.full.f32 %0, %1, %2;" : "=f"(r) : "f"(a), "f"(b));
    return r;
}

__device__ __forceinline__ float2 ld2(const float* p) {
    return __ldg(reinterpret_cast<const float2*>(p));
}
__device__ __forceinline__ void mx(float2& m, float2 v) {
    m.x = fmaxf(m.x, v.x);
    m.y = fmaxf(m.y, v.y);
}

// ---------------- Kernel 1: NCHW -> NHWC transpose (proven, 2.4us) ----------------
__global__ void transpose_in_kernel(const float* __restrict__ x) {
    __shared__ float tile[32][33];
    int b  = blockIdx.z;
    int p0 = blockIdx.x * 32;
    int c0 = blockIdx.y * 32;
    int tx = threadIdx.x;
    int ty = threadIdx.y;

    #pragma unroll
    for (int k = 0; k < 4; ++k) {
        int c = c0 + ty + k * 8;
        int p = p0 + tx;
        if (p < HW)
            tile[ty + k * 8][tx] = x[((size_t)b * C_TOT + c) * HW + p];
    }
    __syncthreads();
    #pragma unroll
    for (int k = 0; k < 4; ++k) {
        int p = p0 + ty + k * 8;
        int c = c0 + tx;
        if (p < HW)
            g_xt[((size_t)b * HW + p) * C_TOT + c] = tile[tx][ty + k * 8];
    }
}

// ---------------- Kernel 2: fused bounds + 1-exposure gather ----------------
__global__ void __launch_bounds__(GTHREADS)
roi_gather_kernel(const float* __restrict__ rois, float* __restrict__ out, int N) {
    __shared__ float s_res[CH * NBINS];   // flat [c][bin], 6272 floats, 25 KB
    __shared__ int   s_hs[POOL_H], s_he[POOL_H], s_ws[POOL_W], s_we[POOL_W];
    __shared__ int   s_b;

    int n    = blockIdx.x;
    int half = blockIdx.y;                 // 128-channel half
    int tid  = threadIdx.x;
    int warp = tid >> 5;
    int lane = tid & 31;

    // --- bounds (exact replica of reference arithmetic, incl. div.full) ---
    if (tid < POOL_H + POOL_W + 1) {
        const float* r = rois + n * 5;
        if (tid == POOL_H + POOL_W) {
            s_b = (int)r[0];
        } else {
            bool is_h = (tid < POOL_H);
            int  i    = is_h ? tid : tid - POOL_H;
            float s1  = rintf(__fmul_rn(r[is_h ? 2 : 1], SPATIAL_SCALE));
            float e1  = rintf(__fmul_rn(r[is_h ? 4 : 3], SPATIAL_SCALE));
            float sz  = fmaxf(__fadd_rn(__fsub_rn(e1, s1), 1.0f), 1.0f);
            float bs  = div_full(sz, is_h ? (float)POOL_H : (float)POOL_W);
            float npx = is_h ? (float)HDIM : (float)WDIM;
            float lo = __fadd_rn(floorf(__fmul_rn((float)i, bs)), s1);
            float hi = __fadd_rn(ceilf(__fmul_rn((float)(i + 1), bs)), s1);
            lo = fminf(fmaxf(lo, 0.0f), npx);
            hi = fminf(fmaxf(hi, 0.0f), npx);
            if (is_h) { s_hs[i] = (int)lo; s_he[i] = (int)hi; }
            else      { s_ws[i] = (int)lo; s_we[i] = (int)hi; }
        }
    }
    __syncthreads();

    // --- gather: unit = (bin, 64-ch sub-half); lane = 2 channels (float2) ---
    const float* xroi = g_xt + (size_t)s_b * (HW * C_TOT) + half * CH;

    for (int u = warp; u < NUNITS; u += NWARPS) {
        int bin = u >> 1;
        int sub = u & 1;
        int ph  = bin / POOL_W;
        int pw  = bin - ph * POOL_W;
        int hs = s_hs[ph], he = s_he[ph];
        int ws = s_ws[pw], we = s_we[pw];
        int wh = he - hs, ww = we - ws;

        float2 m;
        if (wh > 0 && ww > 0 && wh <= 4 && ww <= 4) {
            const float* base = xroi + ((size_t)(hs * WDIM) + ws) * C_TOT
                                     + sub * 64 + lane * 2;
            // Clamped offsets: duplicates are harmless under max.
            int h1 = min(1, wh - 1) * (WDIM * C_TOT);
            int h2 = min(2, wh - 1) * (WDIM * C_TOT);
            int h3 = min(3, wh - 1) * (WDIM * C_TOT);
            int w1 = min(1, ww - 1) * C_TOT;
            int w2 = min(2, ww - 1) * C_TOT;
            int w3 = min(3, ww - 1) * C_TOT;

            // 16 unconditional independent loads -> one latency exposure.
            float2 a00 = ld2(base);
            float2 a01 = ld2(base + w1);
            float2 a02 = ld2(base + w2);
            float2 a03 = ld2(base + w3);
            float2 a10 = ld2(base + h1);
            float2 a11 = ld2(base + h1 + w1);
            float2 a12 = ld2(base + h1 + w2);
            float2 a13 = ld2(base + h1 + w3);
            float2 a20 = ld2(base + h2);
            float2 a21 = ld2(base + h2 + w1);
            float2 a22 = ld2(base + h2 + w2);
            float2 a23 = ld2(base + h2 + w3);
            float2 a30 = ld2(base + h3);
            float2 a31 = ld2(base + h3 + w1);
            float2 a32 = ld2(base + h3 + w2);
            float2 a33 = ld2(base + h3 + w3);

            m = a00;
            mx(m, a01); mx(m, a02); mx(m, a03);
            mx(m, a10); mx(m, a11); mx(m, a12); mx(m, a13);
            mx(m, a20); mx(m, a21); mx(m, a22); mx(m, a23);
            mx(m, a30); mx(m, a31); mx(m, a32); mx(m, a33);
        } else if (wh > 0 && ww > 0) {
            // Fallback (never hit with this data shape, kept for safety).
            m = make_float2(NEG_FLT_MAX, NEG_FLT_MAX);
            const float* rowp = xroi + ((size_t)(hs * WDIM) + ws) * C_TOT
                                     + sub * 64 + lane * 2;
            for (int h = 0; h < wh; ++h) {
                const float* q = rowp;
                for (int w = 0; w < ww; ++w) { mx(m, ld2(q)); q += C_TOT; }
                rowp += WDIM * C_TOT;
            }
        } else {
            m = make_float2(0.f, 0.f);
        }

        int c = sub * 64 + lane * 2;                 // local channel
        s_res[(c + 0) * NBINS + bin] = m.x;
        s_res[(c + 1) * NBINS + bin] = m.y;
    }
    __syncthreads();

    // --- coalesced staged write: flat 6272 floats = 1568 float4 ---
    float* obase = out + (size_t)n * (C_TOT * NBINS) + (size_t)half * (CH * NBINS);
    const float4* src = reinterpret_cast<const float4*>(s_res);
    float4* dst = reinterpret_cast<float4*>(obase);
    #pragma unroll
    for (int k = 0; k < (CH * NBINS) / 4 / GTHREADS + 1; ++k) {
        int i = tid + k * GTHREADS;
        if (i < (CH * NBINS) / 4)
            dst[i] = src[i];
    }
}

extern "C" void kernel_launch(void* const* d_in, const int* in_sizes, int n_in,
                              void* d_out, int out_size) {
    const float* x    = (const float*)d_in[0];   // [B,256,50,50]
    const float* rois = (const float*)d_in[1];   // [N,5]
    float* out = (float*)d_out;                  // [N,256,7,7]

    const int N = in_sizes[1] / 5;
    const int B = in_sizes[0] / (C_TOT * HW);

    dim3 tgrid((HW + 31) / 32, C_TOT / 32, B);
    dim3 tblock(32, 8);
    transpose_in_kernel<<<tgrid, tblock>>>(x);

    dim3 ggrid(N, C_TOT / CH);                   // (128, 2) = 256 blocks
    roi_gather_kernel<<<ggrid, GTHREADS>>>(rois, out, N);
}